// round 14
// baseline (speedup 1.0000x reference)
#include <cuda_runtime.h>
#include <cuda_fp16.h>
#include <math.h>
#include <float.h>

// AutoCorrelation: B=8, L=3072, H=8, E=64
//   mean_value[b,:] = irfft( sum_ch Q_ch * conj(K_ch) ) / 512   (linearity of irfft)
//   packed complex FFT (z = q + i*k) halves FFT count to 4096
//   top40 + softmax per batch; shifts from batch-0 ranks
//   out[b,l,h,d] = sum_k w[b,k] * v[b,(l+shift_k)%L,h,d]

#define NFFT 3072
#define B_   8
#define L_   3072
#define H_   8
#define E_   64
#define ROW  512          // H*E
#define NCH  4096         // B*H*E
#define TOPK 40
#define GCH  8            // channels (FFTs) per block in corr kernel
#define VPAD 1280         // pad rows: wrap once per tap; j*256 offsets (j<6) stay in-range
#define VROWS (NFFT + VPAD)   // 4352 rows x 8 B = 34816 B -> 6 blocks/SM

// ---------------- scratch (device globals; no allocation) ----------------
__device__ float2 g_zt[(size_t)NCH * NFFT];   // transposed (q,k) pairs [channel][t]
__device__ float2 g_acc[B_ * NFFT];           // summed spectra per batch
__device__ float2 g_W[1024];                  // twiddles exp(-2*pi*i*j/3072), j<1024
__device__ float  g_w[B_ * TOPK];             // softmax weights per batch
__device__ int    g_s[TOPK];                  // shifts (batch-0 top-k indices)

__device__ __forceinline__ float2 cmul(float2 a, float2 b) {
    return make_float2(fmaf(a.x, b.x, -a.y * b.y), fmaf(a.x, b.y, a.y * b.x));
}

// bit-casts between half2 and 32-bit words (compile to register moves)
__device__ __forceinline__ unsigned h2_to_u32(__half2 h) {
    return *reinterpret_cast<unsigned*>(&h);
}
__device__ __forceinline__ __half2 u32_to_h2(unsigned u) {
    return *reinterpret_cast<__half2*>(&u);
}

// ---------------- transpose [B,L,H,E] -> [channel][(q,k)] + init ---------
__global__ void __launch_bounds__(256) transpose_k(const float* __restrict__ q,
                                                   const float* __restrict__ k) {
    __shared__ float qt[64 * 33];
    __shared__ float kt[64 * 33];
    int blk = blockIdx.x;          // bh*96 + t-tile
    int tid = threadIdx.x;

    // folded init: zero spectra accumulators + build twiddle table
    if (blk < 96) g_acc[blk * 256 + tid] = make_float2(0.f, 0.f);        // 96*256 = B_*NFFT
    else if (blk < 100) {
        int i = (blk - 96) * 256 + tid;                                   // 0..1023
        float ang = (-2.0f * 3.14159265358979323846f) * (float)i / (float)NFFT;
        float s, c;
        sincosf(ang, &s, &c);
        g_W[i] = make_float2(c, s);
    }

    int bh = blk / 96;             // b*8 + h
    int t0 = (blk % 96) * 32;

    size_t base_in  = (size_t)(bh >> 3) * L_ * ROW + (size_t)(bh & 7) * E_;
    for (int i = tid; i < 2048; i += 256) {
        int tt = i >> 6, e = i & 63;
        size_t a = base_in + (size_t)(t0 + tt) * ROW + e;
        qt[e * 33 + tt] = q[a];
        kt[e * 33 + tt] = k[a];
    }
    __syncthreads();
    float2* dst = g_zt + (size_t)bh * 64 * NFFT;
    for (int i = tid; i < 2048; i += 256) {
        int e = i >> 5, tt = i & 31;
        dst[(size_t)e * NFFT + t0 + tt] = make_float2(qt[e * 33 + tt], kt[e * 33 + tt]);
    }
}

// ---------------- Stockham mixed-radix FFT (3 * 4^5) ---------------------
// First (radix-3) stage fused with the GLOBAL load: reads src[p], src[p+1024],
// src[p+2048] (coalesced), butterflies in registers, writes dst (smem).
template <int NT, bool CONJ>
__device__ __forceinline__ void radix3_g(const float2* __restrict__ src,
                                         float2* __restrict__ dst,
                                         const float2* __restrict__ W, int tid) {
    const float S3 = 0.86602540378443864676f;  // sqrt(3)/2
    for (int p = tid; p < 1024; p += NT) {
        float2 a = src[p], b = src[p + 1024], c = src[p + 2048];
        if (CONJ) { a.y = -a.y; b.y = -b.y; c.y = -c.y; }
        float bpx = b.x + c.x, bpy = b.y + c.y;
        float bmx = b.x - c.x, bmy = b.y - c.y;
        float2 u0 = make_float2(a.x + bpx, a.y + bpy);
        float rx = a.x - 0.5f * bpx, ry = a.y - 0.5f * bpy;
        float2 u1 = make_float2(rx + S3 * bmy, ry - S3 * bmx);
        float2 u2 = make_float2(rx - S3 * bmy, ry + S3 * bmx);
        float2 w1 = W[p];
        float2 w2 = cmul(w1, w1);
        dst[3 * p]     = u0;
        dst[3 * p + 1] = cmul(u1, w1);
        dst[3 * p + 2] = cmul(u2, w2);
    }
    __syncthreads();
}

__device__ __forceinline__ void bfly4(float2 a, float2 b, float2 c, float2 d,
                                      float2& u0, float2& u1, float2& u2, float2& u3) {
    float2 apc = make_float2(a.x + c.x, a.y + c.y);
    float2 amc = make_float2(a.x - c.x, a.y - c.y);
    float2 bpd = make_float2(b.x + d.x, b.y + d.y);
    float2 bmd = make_float2(b.x - d.x, b.y - d.y);
    u0 = make_float2(apc.x + bpd.x, apc.y + bpd.y);
    u2 = make_float2(apc.x - bpd.x, apc.y - bpd.y);
    u1 = make_float2(amc.x + bmd.y, amc.y - bmd.x);  // amc - i*bmd
    u3 = make_float2(amc.x - bmd.y, amc.y + bmd.x);  // amc + i*bmd
}

template <int N_, int S_, int NT>
__device__ __forceinline__ void radix4_stage(const float2* __restrict__ src,
                                             float2* __restrict__ dst,
                                             const float2* __restrict__ W, int tid) {
    constexpr int M_  = N_ / 4;
    constexpr int TWM = NFFT / N_;
    for (int idx = tid; idx < M_ * S_; idx += NT) {
        int p = idx / S_;
        int q = idx - p * S_;
        float2 u0, u1, u2, u3;
        bfly4(src[q + S_ * p], src[q + S_ * (p + M_)],
              src[q + S_ * (p + 2 * M_)], src[q + S_ * (p + 3 * M_)],
              u0, u1, u2, u3);
        float2 w1 = W[p * TWM];
        float2 w2 = cmul(w1, w1);
        float2 w3 = cmul(w2, w1);
        int ob = q + S_ * 4 * p;
        dst[ob]          = u0;
        dst[ob + S_]     = cmul(u1, w1);
        dst[ob + 2 * S_] = cmul(u2, w2);
        dst[ob + 3 * S_] = cmul(u3, w3);
    }
    __syncthreads();
}

// Fused radix-16 = radix4<N_,S_> composed with radix4<N_/4,4*S_>, with the 16
// intermediates register-resident (one smem round + one barrier saved).
// Derivation: stage-B work item (pB, qB=qA+S_*uA) reads stage-A outputs written
// at pA = pB + m*(N_/16); so this thread runs those 4 stage-A butterflies, then
// 4 stage-B butterflies across m, twiddled by W[pB*4*TWM]^uB.
template <int N_, int S_, int NT>
__device__ __forceinline__ void radix16_stage(const float2* __restrict__ src,
                                              float2* __restrict__ dst,
                                              const float2* __restrict__ W, int tid) {
    constexpr int M16 = N_ / 16;
    constexpr int M_  = N_ / 4;
    constexpr int TWM = NFFT / N_;
    for (int idx = tid; idx < M16 * S_; idx += NT) {
        int pB = idx / S_;
        int qA = idx - pB * S_;
        float2 vA[4][4];
#pragma unroll
        for (int m = 0; m < 4; m++) {
            int pA = pB + m * M16;
            float2 u0, u1, u2, u3;
            bfly4(src[qA + S_ * pA], src[qA + S_ * (pA + M_)],
                  src[qA + S_ * (pA + 2 * M_)], src[qA + S_ * (pA + 3 * M_)],
                  u0, u1, u2, u3);
            float2 w1 = W[pA * TWM];
            float2 w2 = cmul(w1, w1);
            float2 w3 = cmul(w2, w1);
            vA[m][0] = u0;
            vA[m][1] = cmul(u1, w1);
            vA[m][2] = cmul(u2, w2);
            vA[m][3] = cmul(u3, w3);
        }
        float2 wB1 = W[pB * 4 * TWM];
        float2 wB2 = cmul(wB1, wB1);
        float2 wB3 = cmul(wB2, wB1);
#pragma unroll
        for (int uA = 0; uA < 4; uA++) {
            float2 u0, u1, u2, u3;
            bfly4(vA[0][uA], vA[1][uA], vA[2][uA], vA[3][uA], u0, u1, u2, u3);
            int ob = qA + S_ * uA + 16 * S_ * pB;
            dst[ob]           = u0;
            dst[ob + 4 * S_]  = cmul(u1, wB1);
            dst[ob + 8 * S_]  = cmul(u2, wB2);
            dst[ob + 12 * S_] = cmul(u3, wB3);
        }
    }
    __syncthreads();
}

// radix-3 already done into buf1; run r16, r16, r4. Result in buf0.
template <int NT>
__device__ __forceinline__ void fft_rest(float2* buf0, float2* buf1,
                                         const float2* __restrict__ W, int tid) {
    radix16_stage<1024, 3, NT>(buf1, buf0, W, tid);
    radix16_stage<64, 48, NT>(buf0, buf1, W, tid);
    radix4_stage<4, 768, NT>(buf1, buf0, W, tid);
}

// ---------------- FFT + spectrum product + per-batch accumulation --------
__global__ void __launch_bounds__(256) corr_k() {
    extern __shared__ float2 sb[];
    float2* buf0 = sb;
    float2* buf1 = sb + NFFT;
    int tid = threadIdx.x;

    float2 pacc[12];
#pragma unroll
    for (int i = 0; i < 12; i++) pacc[i] = make_float2(0.f, 0.f);

    int cbase = blockIdx.x * GCH;
    int b = cbase >> 9;  // 512 channels per batch

    for (int g = 0; g < GCH; g++) {
        const float2* zp = g_zt + (size_t)(cbase + g) * NFFT;
        radix3_g<256, false>(zp, buf1, g_W, tid);   // fused load + first stage
        fft_rest<256>(buf0, buf1, g_W, tid);
#pragma unroll
        for (int i = 0; i < 12; i++) {
            int f = tid + 256 * i;
            float2 Zf = buf0[f];
            int j = (f == 0) ? 0 : (NFFT - f);
            float2 Zc = buf0[j];
            Zc.y = -Zc.y;  // conj(Z[N-f])
            float Qx = 0.5f * (Zf.x + Zc.x), Qy = 0.5f * (Zf.y + Zc.y);
            float Dx = Zf.x - Zc.x,          Dy = Zf.y - Zc.y;
            float Kx = 0.5f * Dy,            Ky = -0.5f * Dx;   // (Z - conj)/2i
            // P = Q * conj(K)
            pacc[i].x += Qx * Kx + Qy * Ky;
            pacc[i].y += Qy * Kx - Qx * Ky;
        }
        // next iteration's radix3_g writes buf1 only (product reads buf0) and
        // ends with a barrier before buf0 is overwritten -> safe.
    }

    float* accf = (float*)(g_acc + (size_t)b * NFFT);
#pragma unroll
    for (int i = 0; i < 12; i++) {
        int f = tid + 256 * i;
        atomicAdd(&accf[2 * f],     pacc[i].x);
        atomicAdd(&accf[2 * f + 1], pacc[i].y);
    }
}

// ---------------- inverse FFT -> mean_value -> top-40 -> softmax ---------
__global__ void __launch_bounds__(512) imean_topk_k() {
    extern __shared__ float2 sb[];
    float2* buf0 = sb;
    float2* buf1 = sb + NFFT;
    __shared__ float swv[16];
    __shared__ int   swi[16];
    __shared__ float topv[TOPK];
    __shared__ int   topi[TOPK];

    int b = blockIdx.x, tid = threadIdx.x;
    int lane = tid & 31, wid = tid >> 5;

    // ifft(X) = conj(FFT(conj(X)))/N; output real -> take .x
    radix3_g<512, true>(g_acc + (size_t)b * NFFT, buf1, g_W, tid);
    fft_rest<512>(buf0, buf1, g_W, tid);

    // register-resident values (ranking unaffected by the positive scale)
    float mv[6];
#pragma unroll
    for (int j = 0; j < 6; j++) mv[j] = buf0[tid + 512 * j].x;

    for (int it = 0; it < TOPK; it++) {
        float best = -FLT_MAX;
        int bi = 0;
#pragma unroll
        for (int j = 0; j < 6; j++)
            if (mv[j] > best) { best = mv[j]; bi = j; }
        int gi = tid + (bi << 9);
#pragma unroll
        for (int off = 16; off > 0; off >>= 1) {
            float ov = __shfl_down_sync(0xffffffffu, best, off);
            int   og = __shfl_down_sync(0xffffffffu, gi, off);
            if (ov > best || (ov == best && og < gi)) { best = ov; gi = og; }
        }
        if (lane == 0) { swv[wid] = best; swi[wid] = gi; }
        __syncthreads();
        if (wid == 0) {
            float v  = (lane < 16) ? swv[lane] : -FLT_MAX;
            int   g2 = (lane < 16) ? swi[lane] : 0x7fffffff;
#pragma unroll
            for (int off = 8; off > 0; off >>= 1) {
                float ov = __shfl_down_sync(0xffffffffu, v, off);
                int   og = __shfl_down_sync(0xffffffffu, g2, off);
                if (ov > v || (ov == v && og < g2)) { v = ov; g2 = og; }
            }
            if (lane == 0) { topv[it] = v; topi[it] = g2; }
        }
        __syncthreads();
        int w = topi[it];
        if ((w & 511) == tid) {
            int j = w >> 9;
#pragma unroll
            for (int jj = 0; jj < 6; jj++)
                if (jj == j) mv[jj] = -FLT_MAX;   // static indexing (no spill)
        }
    }

    if (tid == 0) {
        const float sc = 1.0f / ((float)NFFT * 512.0f);  // 1/N * mean over H*E
        float m = topv[0] * sc;
        float s = 0.f;
        for (int k2 = 0; k2 < TOPK; k2++) s += expf(topv[k2] * sc - m);
        float inv = 1.0f / s;
        for (int k2 = 0; k2 < TOPK; k2++)
            g_w[b * TOPK + k2] = expf(topv[k2] * sc - m) * inv;
        if (b == 0)
            for (int k2 = 0; k2 < TOPK; k2++) g_s[k2] = topi[k2];
    }
}

// ---------------- weighted circular-roll aggregation (fp16 smem) ---------
// v slice lives in smem as fp16 (4 d-channels = 2xhalf2 = 8 B per row) ->
// smem traffic halves vs fp32 and 34.8 KB smem keeps 6 blocks/SM. The
// 1280-row pad makes the circular gather wrap-free: base is wrapped ONCE per
// tap, the 6 register-blocked loads use immediate offsets (LDS.64 [R+imm]).
// Accumulation stays fp32 (only v storage is quantized; ~2e-4 relative).
__global__ void __launch_bounds__(256) agg_k(const float* __restrict__ v,
                                             float* __restrict__ out) {
    extern __shared__ uint2 vsh[];   // [VROWS] rows of 2xhalf2
    __shared__ float ws[TOPK];
    __shared__ int   ss[TOPK];
    int blk = blockIdx.x;            // b*128 + h*16 + dg
    int dg = blk & 15;
    int h  = (blk >> 4) & 7;
    int b  = blk >> 7;
    int d0 = dg * 4;
    int tid = threadIdx.x;

    if (tid < TOPK) { ws[tid] = g_w[b * TOPK + tid]; ss[tid] = g_s[tid]; }

    const float4* vb = (const float4*)(v + (size_t)b * L_ * ROW + h * E_ + d0);
    for (int t = tid; t < VROWS; t += 256) {
        int tt = (t >= NFFT) ? t - NFFT : t;
        float4 val = vb[(size_t)tt * (ROW / 4)];
        uint2 hh;
        hh.x = h2_to_u32(__floats2half2_rn(val.x, val.y));
        hh.y = h2_to_u32(__floats2half2_rn(val.z, val.w));
        vsh[t] = hh;
    }
    __syncthreads();

    float* ob = out + (size_t)b * L_ * ROW + h * E_ + d0;
#pragma unroll
    for (int pass = 0; pass < 2; pass++) {
        const int lbase = pass * 1536;
        float4 acc[6];
#pragma unroll
        for (int j = 0; j < 6; j++) acc[j] = make_float4(0.f, 0.f, 0.f, 0.f);

        for (int k = 0; k < TOPK; k++) {
            int s = ss[k];
            float wk = ws[k];
            int w0 = lbase + tid + s;            // < 2*NFFT
            if (w0 >= NFFT) w0 -= NFFT;          // wrap once; j-offsets hit the pad
            const uint2* base = vsh + w0;
            uint2 t4[6];
#pragma unroll
            for (int j = 0; j < 6; j++)          // immediate offsets: j*256 rows
                t4[j] = base[j * 256];
#pragma unroll
            for (int j = 0; j < 6; j++) {
                float2 lo = __half22float2(u32_to_h2(t4[j].x));
                float2 hi = __half22float2(u32_to_h2(t4[j].y));
                acc[j].x = fmaf(wk, lo.x, acc[j].x);
                acc[j].y = fmaf(wk, lo.y, acc[j].y);
                acc[j].z = fmaf(wk, hi.x, acc[j].z);
                acc[j].w = fmaf(wk, hi.y, acc[j].w);
            }
        }
#pragma unroll
        for (int j = 0; j < 6; j++)
            *(float4*)(ob + (size_t)(lbase + j * 256 + tid) * ROW) = acc[j];
    }
}

// ---------------- launch --------------------------------------------------
extern "C" void kernel_launch(void* const* d_in, const int* in_sizes, int n_in,
                              void* d_out, int out_size) {
    const float* q = (const float*)d_in[0];
    const float* k = (const float*)d_in[1];
    const float* v = (const float*)d_in[2];
    float* out = (float*)d_out;

    // Host-side attribute set: executes immediately, not captured, idempotent.
    cudaFuncSetAttribute(corr_k,        cudaFuncAttributeMaxDynamicSharedMemorySize, 49152);
    cudaFuncSetAttribute(imean_topk_k,  cudaFuncAttributeMaxDynamicSharedMemorySize, 49152);

    transpose_k<<<64 * 96, 256>>>(q, k);
    corr_k<<<NCH / GCH, 256, 2 * NFFT * sizeof(float2)>>>();     // 49152 B
    imean_topk_k<<<B_, 512, 2 * NFFT * sizeof(float2)>>>();      // 49152 B
    agg_k<<<B_ * H_ * (E_ / 4), 256, VROWS * sizeof(uint2)>>>(v, out);  // 34816 B
}

// round 15
// speedup vs baseline: 1.0941x; 1.0941x over previous
#include <cuda_runtime.h>
#include <cuda_fp16.h>
#include <math.h>
#include <float.h>

// AutoCorrelation: B=8, L=3072, H=8, E=64
//   mean_value[b,:] = irfft( sum_ch Q_ch * conj(K_ch) ) / 512   (linearity of irfft)
//   packed complex FFT (z = q + i*k) halves FFT count to 4096
//   top40 + softmax per batch; shifts from batch-0 ranks
//   out[b,l,h,d] = sum_k w[b,k] * v[b,(l+shift_k)%L,h,d]

#define NFFT 3072
#define B_   8
#define L_   3072
#define H_   8
#define E_   64
#define ROW  512          // H*E
#define NCH  4096         // B*H*E
#define TOPK 40
#define GCH  8            // channels (FFTs) per block in corr kernel
#define VPAD 1280         // pad rows: wrap once per tap; j*256 offsets (j<6) stay in-range
#define VROWS (NFFT + VPAD)   // 4352 rows x 8 B = 34816 B -> 6 blocks/SM

// ---------------- scratch (device globals; no allocation) ----------------
__device__ float2 g_zt[(size_t)NCH * NFFT];   // transposed (q,k) pairs [channel][t]
__device__ float2 g_acc[B_ * NFFT];           // summed spectra per batch
__device__ float2 g_W[1024];                  // twiddles exp(-2*pi*i*j/3072), j<1024
__device__ float  g_w[B_ * TOPK];             // softmax weights per batch
__device__ int    g_s[TOPK];                  // shifts (batch-0 top-k indices)

__device__ __forceinline__ float2 cmul(float2 a, float2 b) {
    return make_float2(fmaf(a.x, b.x, -a.y * b.y), fmaf(a.x, b.y, a.y * b.x));
}

// bit-casts between half2 and 32-bit words (compile to register moves)
__device__ __forceinline__ unsigned h2_to_u32(__half2 h) {
    return *reinterpret_cast<unsigned*>(&h);
}
__device__ __forceinline__ __half2 u32_to_h2(unsigned u) {
    return *reinterpret_cast<__half2*>(&u);
}

// Blackwell packed f32x2 FMA: acc = v * w + acc (two fp32 lanes per instr)
__device__ __forceinline__ void ffma2(unsigned long long& acc,
                                      unsigned long long v,
                                      unsigned long long w) {
    asm("fma.rn.f32x2 %0, %1, %2, %0;" : "+l"(acc) : "l"(v), "l"(w));
}
__device__ __forceinline__ unsigned long long f2_to_u64(float2 f) {
    return *reinterpret_cast<unsigned long long*>(&f);
}
__device__ __forceinline__ float2 u64_to_f2(unsigned long long u) {
    return *reinterpret_cast<float2*>(&u);
}

// ---------------- transpose [B,L,H,E] -> [channel][(q,k)] + init ---------
__global__ void __launch_bounds__(256) transpose_k(const float* __restrict__ q,
                                                   const float* __restrict__ k) {
    __shared__ float qt[64 * 33];
    __shared__ float kt[64 * 33];
    int blk = blockIdx.x;          // bh*96 + t-tile
    int tid = threadIdx.x;

    // folded init: zero spectra accumulators + build twiddle table
    if (blk < 96) g_acc[blk * 256 + tid] = make_float2(0.f, 0.f);        // 96*256 = B_*NFFT
    else if (blk < 100) {
        int i = (blk - 96) * 256 + tid;                                   // 0..1023
        float ang = (-2.0f * 3.14159265358979323846f) * (float)i / (float)NFFT;
        float s, c;
        sincosf(ang, &s, &c);
        g_W[i] = make_float2(c, s);
    }

    int bh = blk / 96;             // b*8 + h
    int t0 = (blk % 96) * 32;

    size_t base_in  = (size_t)(bh >> 3) * L_ * ROW + (size_t)(bh & 7) * E_;
    for (int i = tid; i < 2048; i += 256) {
        int tt = i >> 6, e = i & 63;
        size_t a = base_in + (size_t)(t0 + tt) * ROW + e;
        qt[e * 33 + tt] = q[a];
        kt[e * 33 + tt] = k[a];
    }
    __syncthreads();
    float2* dst = g_zt + (size_t)bh * 64 * NFFT;
    for (int i = tid; i < 2048; i += 256) {
        int e = i >> 5, tt = i & 31;
        dst[(size_t)e * NFFT + t0 + tt] = make_float2(qt[e * 33 + tt], kt[e * 33 + tt]);
    }
}

// ---------------- Stockham mixed-radix FFT (3 * 4^5) ---------------------
// First (radix-3) stage fused with the GLOBAL load: reads src[p], src[p+1024],
// src[p+2048] (coalesced), butterflies in registers, writes dst (smem).
template <int NT, bool CONJ>
__device__ __forceinline__ void radix3_g(const float2* __restrict__ src,
                                         float2* __restrict__ dst,
                                         const float2* __restrict__ W, int tid) {
    const float S3 = 0.86602540378443864676f;  // sqrt(3)/2
    for (int p = tid; p < 1024; p += NT) {
        float2 a = src[p], b = src[p + 1024], c = src[p + 2048];
        if (CONJ) { a.y = -a.y; b.y = -b.y; c.y = -c.y; }
        float bpx = b.x + c.x, bpy = b.y + c.y;
        float bmx = b.x - c.x, bmy = b.y - c.y;
        float2 u0 = make_float2(a.x + bpx, a.y + bpy);
        float rx = a.x - 0.5f * bpx, ry = a.y - 0.5f * bpy;
        float2 u1 = make_float2(rx + S3 * bmy, ry - S3 * bmx);
        float2 u2 = make_float2(rx - S3 * bmy, ry + S3 * bmx);
        float2 w1 = W[p];
        float2 w2 = cmul(w1, w1);
        dst[3 * p]     = u0;
        dst[3 * p + 1] = cmul(u1, w1);
        dst[3 * p + 2] = cmul(u2, w2);
    }
    __syncthreads();
}

template <int N_, int S_, int NT>
__device__ __forceinline__ void radix4_stage(const float2* __restrict__ src,
                                             float2* __restrict__ dst,
                                             const float2* __restrict__ W, int tid) {
    constexpr int M_  = N_ / 4;
    constexpr int TWM = NFFT / N_;
    for (int idx = tid; idx < 768; idx += NT) {
        int p = idx / S_;
        int q = idx - p * S_;
        float2 a = src[q + S_ * p];
        float2 b = src[q + S_ * (p + M_)];
        float2 c = src[q + S_ * (p + 2 * M_)];
        float2 d = src[q + S_ * (p + 3 * M_)];
        float2 apc = make_float2(a.x + c.x, a.y + c.y);
        float2 amc = make_float2(a.x - c.x, a.y - c.y);
        float2 bpd = make_float2(b.x + d.x, b.y + d.y);
        float2 bmd = make_float2(b.x - d.x, b.y - d.y);
        float2 u0 = make_float2(apc.x + bpd.x, apc.y + bpd.y);
        float2 u2 = make_float2(apc.x - bpd.x, apc.y - bpd.y);
        float2 u1 = make_float2(amc.x + bmd.y, amc.y - bmd.x);  // amc - i*bmd
        float2 u3 = make_float2(amc.x - bmd.y, amc.y + bmd.x);  // amc + i*bmd
        float2 w1 = W[p * TWM];
        float2 w2 = cmul(w1, w1);
        float2 w3 = cmul(w2, w1);
        int ob = q + S_ * 4 * p;
        dst[ob]          = u0;
        dst[ob + S_]     = cmul(u1, w1);
        dst[ob + 2 * S_] = cmul(u2, w2);
        dst[ob + 3 * S_] = cmul(u3, w3);
    }
    __syncthreads();
}

// radix-3 already done into buf1; run the 5 radix-4 stages. Result in buf0.
template <int NT>
__device__ __forceinline__ void fft_rest(float2* buf0, float2* buf1,
                                         const float2* __restrict__ W, int tid) {
    radix4_stage<1024, 3, NT>(buf1, buf0, W, tid);
    radix4_stage<256, 12, NT>(buf0, buf1, W, tid);
    radix4_stage<64, 48, NT>(buf1, buf0, W, tid);
    radix4_stage<16, 192, NT>(buf0, buf1, W, tid);
    radix4_stage<4, 768, NT>(buf1, buf0, W, tid);
}

// ---------------- FFT + spectrum product + per-batch accumulation --------
__global__ void __launch_bounds__(256) corr_k() {
    extern __shared__ float2 sb[];
    float2* buf0 = sb;
    float2* buf1 = sb + NFFT;
    int tid = threadIdx.x;

    float2 pacc[12];
#pragma unroll
    for (int i = 0; i < 12; i++) pacc[i] = make_float2(0.f, 0.f);

    int cbase = blockIdx.x * GCH;
    int b = cbase >> 9;  // 512 channels per batch

    for (int g = 0; g < GCH; g++) {
        const float2* zp = g_zt + (size_t)(cbase + g) * NFFT;
        radix3_g<256, false>(zp, buf1, g_W, tid);   // fused load + first stage
        fft_rest<256>(buf0, buf1, g_W, tid);
#pragma unroll
        for (int i = 0; i < 12; i++) {
            int f = tid + 256 * i;
            float2 Zf = buf0[f];
            int j = (f == 0) ? 0 : (NFFT - f);
            float2 Zc = buf0[j];
            Zc.y = -Zc.y;  // conj(Z[N-f])
            float Qx = 0.5f * (Zf.x + Zc.x), Qy = 0.5f * (Zf.y + Zc.y);
            float Dx = Zf.x - Zc.x,          Dy = Zf.y - Zc.y;
            float Kx = 0.5f * Dy,            Ky = -0.5f * Dx;   // (Z - conj)/2i
            // P = Q * conj(K)
            pacc[i].x += Qx * Kx + Qy * Ky;
            pacc[i].y += Qy * Kx - Qx * Ky;
        }
        // next iteration's radix3_g writes buf1 only (product reads buf0) and
        // ends with a barrier before buf0 is overwritten -> safe.
    }

    float* accf = (float*)(g_acc + (size_t)b * NFFT);
#pragma unroll
    for (int i = 0; i < 12; i++) {
        int f = tid + 256 * i;
        atomicAdd(&accf[2 * f],     pacc[i].x);
        atomicAdd(&accf[2 * f + 1], pacc[i].y);
    }
}

// ---------------- inverse FFT -> mean_value -> top-40 -> softmax ---------
__global__ void __launch_bounds__(512) imean_topk_k() {
    extern __shared__ float2 sb[];
    float2* buf0 = sb;
    float2* buf1 = sb + NFFT;
    __shared__ float swv[16];
    __shared__ int   swi[16];
    __shared__ float topv[TOPK];
    __shared__ int   topi[TOPK];

    int b = blockIdx.x, tid = threadIdx.x;
    int lane = tid & 31, wid = tid >> 5;

    // ifft(X) = conj(FFT(conj(X)))/N; output real -> take .x
    radix3_g<512, true>(g_acc + (size_t)b * NFFT, buf1, g_W, tid);
    fft_rest<512>(buf0, buf1, g_W, tid);

    // register-resident values (ranking unaffected by the positive scale)
    float mv[6];
#pragma unroll
    for (int j = 0; j < 6; j++) mv[j] = buf0[tid + 512 * j].x;

    for (int it = 0; it < TOPK; it++) {
        float best = -FLT_MAX;
        int bi = 0;
#pragma unroll
        for (int j = 0; j < 6; j++)
            if (mv[j] > best) { best = mv[j]; bi = j; }
        int gi = tid + (bi << 9);
#pragma unroll
        for (int off = 16; off > 0; off >>= 1) {
            float ov = __shfl_down_sync(0xffffffffu, best, off);
            int   og = __shfl_down_sync(0xffffffffu, gi, off);
            if (ov > best || (ov == best && og < gi)) { best = ov; gi = og; }
        }
        if (lane == 0) { swv[wid] = best; swi[wid] = gi; }
        __syncthreads();
        if (wid == 0) {
            float v  = (lane < 16) ? swv[lane] : -FLT_MAX;
            int   g2 = (lane < 16) ? swi[lane] : 0x7fffffff;
#pragma unroll
            for (int off = 8; off > 0; off >>= 1) {
                float ov = __shfl_down_sync(0xffffffffu, v, off);
                int   og = __shfl_down_sync(0xffffffffu, g2, off);
                if (ov > v || (ov == v && og < g2)) { v = ov; g2 = og; }
            }
            if (lane == 0) { topv[it] = v; topi[it] = g2; }
        }
        __syncthreads();
        int w = topi[it];
        if ((w & 511) == tid) {
            int j = w >> 9;
#pragma unroll
            for (int jj = 0; jj < 6; jj++)
                if (jj == j) mv[jj] = -FLT_MAX;   // static indexing (no spill)
        }
    }

    if (tid == 0) {
        const float sc = 1.0f / ((float)NFFT * 512.0f);  // 1/N * mean over H*E
        float m = topv[0] * sc;
        float s = 0.f;
        for (int k2 = 0; k2 < TOPK; k2++) s += expf(topv[k2] * sc - m);
        float inv = 1.0f / s;
        for (int k2 = 0; k2 < TOPK; k2++)
            g_w[b * TOPK + k2] = expf(topv[k2] * sc - m) * inv;
        if (b == 0)
            for (int k2 = 0; k2 < TOPK; k2++) g_s[k2] = topi[k2];
    }
}

// ---------------- weighted circular-roll aggregation (fp16 smem) ---------
// v slice lives in smem as fp16 (4 d-channels = 2xhalf2 = 8 B per row) ->
// smem traffic halves vs fp32 and 34.8 KB smem keeps 6 blocks/SM. The
// 1280-row pad makes the circular gather wrap-free: base is wrapped ONCE per
// tap, the 6 register-blocked loads use immediate offsets (LDS.64 [R+imm]).
// Accumulation fp32 via packed fma.rn.f32x2 (12 FFMA2 replace 24 FFMA per
// tap -> ~27% fewer issue slots in the mainloop; rounding identical per lane).
__global__ void __launch_bounds__(256) agg_k(const float* __restrict__ v,
                                             float* __restrict__ out) {
    extern __shared__ uint2 vsh[];   // [VROWS] rows of 2xhalf2
    __shared__ float ws[TOPK];
    __shared__ int   ss[TOPK];
    int blk = blockIdx.x;            // b*128 + h*16 + dg
    int dg = blk & 15;
    int h  = (blk >> 4) & 7;
    int b  = blk >> 7;
    int d0 = dg * 4;
    int tid = threadIdx.x;

    if (tid < TOPK) { ws[tid] = g_w[b * TOPK + tid]; ss[tid] = g_s[tid]; }

    const float4* vb = (const float4*)(v + (size_t)b * L_ * ROW + h * E_ + d0);
    for (int t = tid; t < VROWS; t += 256) {
        int tt = (t >= NFFT) ? t - NFFT : t;
        float4 val = vb[(size_t)tt * (ROW / 4)];
        uint2 hh;
        hh.x = h2_to_u32(__floats2half2_rn(val.x, val.y));
        hh.y = h2_to_u32(__floats2half2_rn(val.z, val.w));
        vsh[t] = hh;
    }
    __syncthreads();

    float* ob = out + (size_t)b * L_ * ROW + h * E_ + d0;
#pragma unroll
    for (int pass = 0; pass < 2; pass++) {
        const int lbase = pass * 1536;
        unsigned long long acc[6][2];
#pragma unroll
        for (int j = 0; j < 6; j++) { acc[j][0] = 0ull; acc[j][1] = 0ull; }

        for (int k = 0; k < TOPK; k++) {
            int s = ss[k];
            float wk = ws[k];
            unsigned long long wpk;
            asm("mov.b64 %0, {%1, %1};" : "=l"(wpk) : "f"(wk));
            int w0 = lbase + tid + s;            // < 2*NFFT
            if (w0 >= NFFT) w0 -= NFFT;          // wrap once; j-offsets hit the pad
            const uint2* base = vsh + w0;
            uint2 t4[6];
#pragma unroll
            for (int j = 0; j < 6; j++)          // immediate offsets: j*256 rows
                t4[j] = base[j * 256];
#pragma unroll
            for (int j = 0; j < 6; j++) {
                float2 lo = __half22float2(u32_to_h2(t4[j].x));
                float2 hi = __half22float2(u32_to_h2(t4[j].y));
                ffma2(acc[j][0], f2_to_u64(lo), wpk);
                ffma2(acc[j][1], f2_to_u64(hi), wpk);
            }
        }
#pragma unroll
        for (int j = 0; j < 6; j++) {
            float2 lo = u64_to_f2(acc[j][0]);
            float2 hi = u64_to_f2(acc[j][1]);
            *(float4*)(ob + (size_t)(lbase + j * 256 + tid) * ROW) =
                make_float4(lo.x, lo.y, hi.x, hi.y);
        }
    }
}

// ---------------- launch --------------------------------------------------
extern "C" void kernel_launch(void* const* d_in, const int* in_sizes, int n_in,
                              void* d_out, int out_size) {
    const float* q = (const float*)d_in[0];
    const float* k = (const float*)d_in[1];
    const float* v = (const float*)d_in[2];
    float* out = (float*)d_out;

    // Host-side attribute set: executes immediately, not captured, idempotent.
    cudaFuncSetAttribute(corr_k,        cudaFuncAttributeMaxDynamicSharedMemorySize, 49152);
    cudaFuncSetAttribute(imean_topk_k,  cudaFuncAttributeMaxDynamicSharedMemorySize, 49152);

    transpose_k<<<64 * 96, 256>>>(q, k);
    corr_k<<<NCH / GCH, 256, 2 * NFFT * sizeof(float2)>>>();     // 49152 B
    imean_topk_k<<<B_, 512, 2 * NFFT * sizeof(float2)>>>();      // 49152 B
    agg_k<<<B_ * H_ * (E_ / 4), 256, VROWS * sizeof(uint2)>>>(v, out);  // 34816 B
}

// round 16
// speedup vs baseline: 1.1377x; 1.0399x over previous
#include <cuda_runtime.h>
#include <cuda_fp16.h>
#include <math.h>
#include <float.h>

// AutoCorrelation: B=8, L=3072, H=8, E=64
//   mean_value[b,:] = irfft( sum_ch Q_ch * conj(K_ch) ) / 512   (linearity of irfft)
//   packed complex FFT (z = q + i*k) halves FFT count to 4096
//   top40 + softmax per batch; shifts from batch-0 ranks
//   out[b,l,h,d] = sum_k w[b,k] * v[b,(l+shift_k)%L,h,d]

#define NFFT 3072
#define B_   8
#define L_   3072
#define H_   8
#define E_   64
#define ROW  512          // H*E
#define NCH  4096         // B*H*E
#define TOPK 40
#define GCH  8            // channels (FFTs) per block in corr kernel
#define VPAD 1280         // pad rows: wrap once per tap; j*256 offsets (j<6) stay in-range
#define VROWS (NFFT + VPAD)   // 4352 rows x 8 B = 34816 B -> 6 blocks/SM

// ---------------- scratch (device globals; no allocation) ----------------
__device__ float2 g_zt[(size_t)NCH * NFFT];   // transposed (q,k) pairs [channel][t]
__device__ float2 g_acc[B_ * NFFT];           // summed spectra per batch
__device__ float2 g_W[1024];                  // twiddles exp(-2*pi*i*j/3072), j<1024
__device__ float  g_w[B_ * TOPK];             // softmax weights per batch
__device__ int    g_s[TOPK];                  // shifts (batch-0 top-k indices)

__device__ __forceinline__ float2 cmul(float2 a, float2 b) {
    return make_float2(fmaf(a.x, b.x, -a.y * b.y), fmaf(a.x, b.y, a.y * b.x));
}

// bit-casts between half2 and 32-bit words (compile to register moves)
__device__ __forceinline__ unsigned h2_to_u32(__half2 h) {
    return *reinterpret_cast<unsigned*>(&h);
}
__device__ __forceinline__ __half2 u32_to_h2(unsigned u) {
    return *reinterpret_cast<__half2*>(&u);
}

// ---------------- transpose [B,L,H,E] -> [channel][(q,k)] + init ---------
__global__ void __launch_bounds__(256) transpose_k(const float* __restrict__ q,
                                                   const float* __restrict__ k) {
    __shared__ float qt[64 * 33];
    __shared__ float kt[64 * 33];
    int blk = blockIdx.x;          // bh*96 + t-tile
    int tid = threadIdx.x;

    // folded init: zero spectra accumulators + build twiddle table
    if (blk < 96) g_acc[blk * 256 + tid] = make_float2(0.f, 0.f);        // 96*256 = B_*NFFT
    else if (blk < 100) {
        int i = (blk - 96) * 256 + tid;                                   // 0..1023
        float ang = (-2.0f * 3.14159265358979323846f) * (float)i / (float)NFFT;
        float s, c;
        sincosf(ang, &s, &c);
        g_W[i] = make_float2(c, s);
    }

    int bh = blk / 96;             // b*8 + h
    int t0 = (blk % 96) * 32;

    size_t base_in  = (size_t)(bh >> 3) * L_ * ROW + (size_t)(bh & 7) * E_;
    for (int i = tid; i < 2048; i += 256) {
        int tt = i >> 6, e = i & 63;
        size_t a = base_in + (size_t)(t0 + tt) * ROW + e;
        qt[e * 33 + tt] = q[a];
        kt[e * 33 + tt] = k[a];
    }
    __syncthreads();
    float2* dst = g_zt + (size_t)bh * 64 * NFFT;
    for (int i = tid; i < 2048; i += 256) {
        int e = i >> 5, tt = i & 31;
        dst[(size_t)e * NFFT + t0 + tt] = make_float2(qt[e * 33 + tt], kt[e * 33 + tt]);
    }
}

// ---------------- Stockham mixed-radix FFT (12 * 4^4) --------------------
// First stage is a fused radix-12 (= radix-3 composed with radix-4<1024,3>)
// fed DIRECTLY from global memory: 256 work items (one per thread at NT=256),
// 12 coalesced global loads each (addresses p4 + 256*j), 12 register
// intermediates, 12 smem stores. Arithmetic is operation-identical to the
// former radix3_g + radix4_stage<1024,3> pair.
__device__ __forceinline__ void bfly4(float2 a, float2 b, float2 c, float2 d,
                                      float2& u0, float2& u1, float2& u2, float2& u3) {
    float2 apc = make_float2(a.x + c.x, a.y + c.y);
    float2 amc = make_float2(a.x - c.x, a.y - c.y);
    float2 bpd = make_float2(b.x + d.x, b.y + d.y);
    float2 bmd = make_float2(b.x - d.x, b.y - d.y);
    u0 = make_float2(apc.x + bpd.x, apc.y + bpd.y);
    u2 = make_float2(apc.x - bpd.x, apc.y - bpd.y);
    u1 = make_float2(amc.x + bmd.y, amc.y - bmd.x);  // amc - i*bmd
    u3 = make_float2(amc.x - bmd.y, amc.y + bmd.x);  // amc + i*bmd
}

template <int NT, bool CONJ>
__device__ __forceinline__ void radix12_g(const float2* __restrict__ src,
                                          float2* __restrict__ dst,
                                          const float2* __restrict__ W, int tid) {
    const float S3 = 0.86602540378443864676f;  // sqrt(3)/2
    for (int p4 = tid; p4 < 256; p4 += NT) {
        float2 v[4][3];   // [m][q4] radix-3 outputs, twiddled
#pragma unroll
        for (int m = 0; m < 4; m++) {
            int p = p4 + 256 * m;
            float2 a = src[p], b = src[p + 1024], c = src[p + 2048];
            if (CONJ) { a.y = -a.y; b.y = -b.y; c.y = -c.y; }
            float bpx = b.x + c.x, bpy = b.y + c.y;
            float bmx = b.x - c.x, bmy = b.y - c.y;
            float2 u0 = make_float2(a.x + bpx, a.y + bpy);
            float rx = a.x - 0.5f * bpx, ry = a.y - 0.5f * bpy;
            float2 u1 = make_float2(rx + S3 * bmy, ry - S3 * bmx);
            float2 u2 = make_float2(rx - S3 * bmy, ry + S3 * bmx);
            float2 w1 = W[p];
            float2 w2 = cmul(w1, w1);
            v[m][0] = u0;
            v[m][1] = cmul(u1, w1);
            v[m][2] = cmul(u2, w2);
        }
        float2 wB1 = W[3 * p4];
        float2 wB2 = cmul(wB1, wB1);
        float2 wB3 = cmul(wB2, wB1);
#pragma unroll
        for (int q4 = 0; q4 < 3; q4++) {
            float2 u0, u1, u2, u3;
            bfly4(v[0][q4], v[1][q4], v[2][q4], v[3][q4], u0, u1, u2, u3);
            int ob = 12 * p4 + q4;
            dst[ob]     = u0;
            dst[ob + 3] = cmul(u1, wB1);
            dst[ob + 6] = cmul(u2, wB2);
            dst[ob + 9] = cmul(u3, wB3);
        }
    }
    __syncthreads();
}

template <int N_, int S_, int NT>
__device__ __forceinline__ void radix4_stage(const float2* __restrict__ src,
                                             float2* __restrict__ dst,
                                             const float2* __restrict__ W, int tid) {
    constexpr int M_  = N_ / 4;
    constexpr int TWM = NFFT / N_;
    for (int idx = tid; idx < 768; idx += NT) {
        int p = idx / S_;
        int q = idx - p * S_;
        float2 u0, u1, u2, u3;
        bfly4(src[q + S_ * p], src[q + S_ * (p + M_)],
              src[q + S_ * (p + 2 * M_)], src[q + S_ * (p + 3 * M_)],
              u0, u1, u2, u3);
        float2 w1 = W[p * TWM];
        float2 w2 = cmul(w1, w1);
        float2 w3 = cmul(w2, w1);
        int ob = q + S_ * 4 * p;
        dst[ob]          = u0;
        dst[ob + S_]     = cmul(u1, w1);
        dst[ob + 2 * S_] = cmul(u2, w2);
        dst[ob + 3 * S_] = cmul(u3, w3);
    }
    __syncthreads();
}

// radix-12 already done into buf1; run the 4 radix-4 stages. Result in buf1.
template <int NT>
__device__ __forceinline__ void fft_rest(float2* buf0, float2* buf1,
                                         const float2* __restrict__ W, int tid) {
    radix4_stage<256, 12, NT>(buf1, buf0, W, tid);
    radix4_stage<64, 48, NT>(buf0, buf1, W, tid);
    radix4_stage<16, 192, NT>(buf1, buf0, W, tid);
    radix4_stage<4, 768, NT>(buf0, buf1, W, tid);
}

// ---------------- FFT + spectrum product + per-batch accumulation --------
__global__ void __launch_bounds__(256) corr_k() {
    extern __shared__ float2 sb[];
    float2* buf0 = sb;
    float2* buf1 = sb + NFFT;
    int tid = threadIdx.x;

    float2 pacc[12];
#pragma unroll
    for (int i = 0; i < 12; i++) pacc[i] = make_float2(0.f, 0.f);

    int cbase = blockIdx.x * GCH;
    int b = cbase >> 9;  // 512 channels per batch

    for (int g = 0; g < GCH; g++) {
        const float2* zp = g_zt + (size_t)(cbase + g) * NFFT;
        radix12_g<256, false>(zp, buf1, g_W, tid);   // fused global load + r3+r4
        fft_rest<256>(buf0, buf1, g_W, tid);         // result in buf1
#pragma unroll
        for (int i = 0; i < 12; i++) {
            int f = tid + 256 * i;
            float2 Zf = buf1[f];
            int j = (f == 0) ? 0 : (NFFT - f);
            float2 Zc = buf1[j];
            Zc.y = -Zc.y;  // conj(Z[N-f])
            float Qx = 0.5f * (Zf.x + Zc.x), Qy = 0.5f * (Zf.y + Zc.y);
            float Dx = Zf.x - Zc.x,          Dy = Zf.y - Zc.y;
            float Kx = 0.5f * Dy,            Ky = -0.5f * Dx;   // (Z - conj)/2i
            // P = Q * conj(K)
            pacc[i].x += Qx * Kx + Qy * Ky;
            pacc[i].y += Qy * Kx - Qx * Ky;
        }
        __syncthreads();   // product reads buf1; next radix12_g writes buf1
    }

    float* accf = (float*)(g_acc + (size_t)b * NFFT);
#pragma unroll
    for (int i = 0; i < 12; i++) {
        int f = tid + 256 * i;
        atomicAdd(&accf[2 * f],     pacc[i].x);
        atomicAdd(&accf[2 * f + 1], pacc[i].y);
    }
}

// ---------------- inverse FFT -> mean_value -> top-40 -> softmax ---------
__global__ void __launch_bounds__(512) imean_topk_k() {
    extern __shared__ float2 sb[];
    float2* buf0 = sb;
    float2* buf1 = sb + NFFT;
    __shared__ float swv[16];
    __shared__ int   swi[16];
    __shared__ float topv[TOPK];
    __shared__ int   topi[TOPK];

    int b = blockIdx.x, tid = threadIdx.x;
    int lane = tid & 31, wid = tid >> 5;

    // ifft(X) = conj(FFT(conj(X)))/N; output real -> take .x
    radix12_g<512, true>(g_acc + (size_t)b * NFFT, buf1, g_W, tid);
    fft_rest<512>(buf0, buf1, g_W, tid);   // result in buf1

    // register-resident values (ranking unaffected by the positive scale)
    float mv[6];
#pragma unroll
    for (int j = 0; j < 6; j++) mv[j] = buf1[tid + 512 * j].x;

    for (int it = 0; it < TOPK; it++) {
        float best = -FLT_MAX;
        int bi = 0;
#pragma unroll
        for (int j = 0; j < 6; j++)
            if (mv[j] > best) { best = mv[j]; bi = j; }
        int gi = tid + (bi << 9);
#pragma unroll
        for (int off = 16; off > 0; off >>= 1) {
            float ov = __shfl_down_sync(0xffffffffu, best, off);
            int   og = __shfl_down_sync(0xffffffffu, gi, off);
            if (ov > best || (ov == best && og < gi)) { best = ov; gi = og; }
        }
        if (lane == 0) { swv[wid] = best; swi[wid] = gi; }
        __syncthreads();
        if (wid == 0) {
            float v  = (lane < 16) ? swv[lane] : -FLT_MAX;
            int   g2 = (lane < 16) ? swi[lane] : 0x7fffffff;
#pragma unroll
            for (int off = 8; off > 0; off >>= 1) {
                float ov = __shfl_down_sync(0xffffffffu, v, off);
                int   og = __shfl_down_sync(0xffffffffu, g2, off);
                if (ov > v || (ov == v && og < g2)) { v = ov; g2 = og; }
            }
            if (lane == 0) { topv[it] = v; topi[it] = g2; }
        }
        __syncthreads();
        int w = topi[it];
        if ((w & 511) == tid) {
            int j = w >> 9;
#pragma unroll
            for (int jj = 0; jj < 6; jj++)
                if (jj == j) mv[jj] = -FLT_MAX;   // static indexing (no spill)
        }
    }

    if (tid == 0) {
        const float sc = 1.0f / ((float)NFFT * 512.0f);  // 1/N * mean over H*E
        float m = topv[0] * sc;
        float s = 0.f;
        for (int k2 = 0; k2 < TOPK; k2++) s += expf(topv[k2] * sc - m);
        float inv = 1.0f / s;
        for (int k2 = 0; k2 < TOPK; k2++)
            g_w[b * TOPK + k2] = expf(topv[k2] * sc - m) * inv;
        if (b == 0)
            for (int k2 = 0; k2 < TOPK; k2++) g_s[k2] = topi[k2];
    }
}

// ---------------- weighted circular-roll aggregation (fp16 smem) ---------
// v slice lives in smem as fp16 (4 d-channels = 2xhalf2 = 8 B per row) ->
// smem traffic halves vs fp32 and 34.8 KB smem keeps 6 blocks/SM. The
// 1280-row pad makes the circular gather wrap-free: base is wrapped ONCE per
// tap, the 6 register-blocked loads use immediate offsets (LDS.64 [R+imm]).
// Accumulation stays fp32 scalar FMA (R13 form — the FFMA2 variant measured
// slower; this kernel is L1-wavefront/latency bound, not issue bound).
__global__ void __launch_bounds__(256) agg_k(const float* __restrict__ v,
                                             float* __restrict__ out) {
    extern __shared__ uint2 vsh[];   // [VROWS] rows of 2xhalf2
    __shared__ float ws[TOPK];
    __shared__ int   ss[TOPK];
    int blk = blockIdx.x;            // b*128 + h*16 + dg
    int dg = blk & 15;
    int h  = (blk >> 4) & 7;
    int b  = blk >> 7;
    int d0 = dg * 4;
    int tid = threadIdx.x;

    if (tid < TOPK) { ws[tid] = g_w[b * TOPK + tid]; ss[tid] = g_s[tid]; }

    const float4* vb = (const float4*)(v + (size_t)b * L_ * ROW + h * E_ + d0);
    for (int t = tid; t < VROWS; t += 256) {
        int tt = (t >= NFFT) ? t - NFFT : t;
        float4 val = vb[(size_t)tt * (ROW / 4)];
        uint2 hh;
        hh.x = h2_to_u32(__floats2half2_rn(val.x, val.y));
        hh.y = h2_to_u32(__floats2half2_rn(val.z, val.w));
        vsh[t] = hh;
    }
    __syncthreads();

    float* ob = out + (size_t)b * L_ * ROW + h * E_ + d0;
#pragma unroll
    for (int pass = 0; pass < 2; pass++) {
        const int lbase = pass * 1536;
        float4 acc[6];
#pragma unroll
        for (int j = 0; j < 6; j++) acc[j] = make_float4(0.f, 0.f, 0.f, 0.f);

        for (int k = 0; k < TOPK; k++) {
            int s = ss[k];
            float wk = ws[k];
            int w0 = lbase + tid + s;            // < 2*NFFT
            if (w0 >= NFFT) w0 -= NFFT;          // wrap once; j-offsets hit the pad
            const uint2* base = vsh + w0;
            uint2 t4[6];
#pragma unroll
            for (int j = 0; j < 6; j++)          // immediate offsets: j*256 rows
                t4[j] = base[j * 256];
#pragma unroll
            for (int j = 0; j < 6; j++) {
                float2 lo = __half22float2(u32_to_h2(t4[j].x));
                float2 hi = __half22float2(u32_to_h2(t4[j].y));
                acc[j].x = fmaf(wk, lo.x, acc[j].x);
                acc[j].y = fmaf(wk, lo.y, acc[j].y);
                acc[j].z = fmaf(wk, hi.x, acc[j].z);
                acc[j].w = fmaf(wk, hi.y, acc[j].w);
            }
        }
#pragma unroll
        for (int j = 0; j < 6; j++)
            *(float4*)(ob + (size_t)(lbase + j * 256 + tid) * ROW) = acc[j];
    }
}

// ---------------- launch --------------------------------------------------
extern "C" void kernel_launch(void* const* d_in, const int* in_sizes, int n_in,
                              void* d_out, int out_size) {
    const float* q = (const float*)d_in[0];
    const float* k = (const float*)d_in[1];
    const float* v = (const float*)d_in[2];
    float* out = (float*)d_out;

    // Host-side attribute set: executes immediately, not captured, idempotent.
    cudaFuncSetAttribute(corr_k,        cudaFuncAttributeMaxDynamicSharedMemorySize, 49152);
    cudaFuncSetAttribute(imean_topk_k,  cudaFuncAttributeMaxDynamicSharedMemorySize, 49152);

    transpose_k<<<64 * 96, 256>>>(q, k);
    corr_k<<<NCH / GCH, 256, 2 * NFFT * sizeof(float2)>>>();     // 49152 B
    imean_topk_k<<<B_, 512, 2 * NFFT * sizeof(float2)>>>();      // 49152 B
    agg_k<<<B_ * H_ * (E_ / 4), 256, VROWS * sizeof(uint2)>>>(v, out);  // 34816 B
}